// round 15
// baseline (speedup 1.0000x reference)
#include <cuda_runtime.h>
#include <cuda_fp16.h>
#include <math.h>
#include <stdint.h>

#define NN 50000
#define NE 640000
#define DIN 128
#define DH1 128
#define DH2 256
#define NT1 (3 * DH1)   // 384
#define NT2 (3 * DH2)   // 768
#define SPLIT_ROWS 25088          // 196 blocks of 128
#define SPLIT_YB 196

// ---------------- device scratch ----------------
__device__ __half   g_xh[NN * DIN];
__device__ __half   g_xlh1[NN * DH1];
__device__ float    g_c1[NN * 2 * DH1];
__device__ __half   g_h1h[NN * DH1];
__device__ __half   g_xlh2[NN * DH2];
__device__ float    g_c2[NN * 2 * DH2];
__device__ __half   g_W1h[NT1 * DIN];
__device__ __half   g_W2h[NT2 * DH1];
__device__ float    g_b1p[NT1];
__device__ float    g_b2p[NT2];
__device__ int      g_rowptr[NN + 1];
__device__ int      g_hist[NN];
__device__ int      g_cursor[NN];
__device__ int      g_srcs[NE];
__device__ int      g_is64;
#define SCAN_NB 98
__device__ int      g_bsum[SCAN_NB];
__device__ int      g_boff[SCAN_NB];

__device__ __forceinline__ void cp_async16(uint32_t dst, const void* src) {
    asm volatile("cp.async.cg.shared.global [%0], [%1], 16;" :: "r"(dst), "l"(src));
}
#define CP_COMMIT() asm volatile("cp.async.commit_group;" ::: "memory")
#define CP_WAIT0()  asm volatile("cp.async.wait_group 0;" ::: "memory")

// ---------------- edge_index dtype detection ----------------
__global__ void detect_kernel(const unsigned int* __restrict__ w) {
    __shared__ int any_nonzero;
    if (threadIdx.x == 0) any_nonzero = 0;
    __syncthreads();
    unsigned int v = w[2 * threadIdx.x + 1];
    if (v != 0u) atomicOr(&any_nonzero, 1);
    __syncthreads();
    if (threadIdx.x == 0) g_is64 = any_nonzero ? 0 : 1;
}
__device__ __forceinline__ int load_idx(const void* ei, int i) {
    return g_is64 ? (int)((const long long*)ei)[i] : ((const int*)ei)[i];
}

// ---------------- x -> fp16 ----------------
__global__ void xconv_kernel(const float* __restrict__ x) {
    int i = blockIdx.x * blockDim.x + threadIdx.x;
    if (i < NN * DIN / 4) {
        float4 v = ((const float4*)x)[i];
        __half2 h0 = __floats2half2_rn(v.x, v.y);
        __half2 h1 = __floats2half2_rn(v.z, v.w);
        uint2 u;
        u.x = *(unsigned*)&h0; u.y = *(unsigned*)&h1;
        ((uint2*)g_xh)[i] = u;
    }
}

// ---------------- weight packing ----------------
__global__ void pack_all_kernel(
    const float* __restrict__ Wl1, const float* __restrict__ Wr1,
    const float* __restrict__ Wres1, const float* __restrict__ b1,
    const float* __restrict__ Wl2, const float* __restrict__ Wr2,
    const float* __restrict__ Wres2, const float* __restrict__ b2)
{
    int idx = blockIdx.x * blockDim.x + threadIdx.x;
    const int S1 = NT1 * DIN;
    const int S2 = NT2 * DH1;
    if (idx < S1) {
        int n = idx / DIN, k = idx % DIN;
        float v = (n < DH1) ? Wl1[k * DH1 + n]
                : (n < 2 * DH1) ? Wr1[k * DH1 + (n - DH1)]
                : Wres1[k * DH1 + (n - 2 * DH1)];
        g_W1h[idx] = __float2half(v);
    } else if (idx < S1 + S2) {
        int j = idx - S1;
        int n = j / DH1, k = j % DH1;
        float v = (n < DH2) ? Wl2[k * DH2 + n]
                : (n < 2 * DH2) ? Wr2[k * DH2 + (n - DH2)]
                : Wres2[k * DH2 + (n - 2 * DH2)];
        g_W2h[j] = __float2half(v);
    }
    if (idx < NT1) g_b1p[idx] = (idx < 2 * DH1) ? 0.f : b1[idx - 2 * DH1];
    if (idx < NT2) g_b2p[idx] = (idx < 2 * DH2) ? 0.f : b2[idx - 2 * DH2];
}

// ---------------- CSR build ----------------
__global__ void hist_kernel(const void* __restrict__ ei) {
    int e = blockIdx.x * blockDim.x + threadIdx.x;
    if (e < NE) atomicAdd(&g_hist[load_idx(ei, NE + e)], 1);
}
__global__ void scan_pass1() {
    __shared__ int sh[512];
    int t = threadIdx.x;
    int i = blockIdx.x * 512 + t;
    int v = (i < NN) ? g_hist[i] : 0;
    sh[t] = v;
    __syncthreads();
    for (int off = 1; off < 512; off <<= 1) {
        int u = (t >= off) ? sh[t - off] : 0;
        __syncthreads();
        sh[t] += u;
        __syncthreads();
    }
    if (i < NN) g_rowptr[i] = sh[t] - v;
    if (t == 511) g_bsum[blockIdx.x] = sh[511];
}
__global__ void scan_pass2() {
    __shared__ int sh[128];
    int t = threadIdx.x;
    int v = (t < SCAN_NB) ? g_bsum[t] : 0;
    sh[t] = v;
    __syncthreads();
    for (int off = 1; off < 128; off <<= 1) {
        int u = (t >= off) ? sh[t - off] : 0;
        __syncthreads();
        sh[t] += u;
        __syncthreads();
    }
    if (t < SCAN_NB) g_boff[t] = sh[t] - v;
    if (t == 0) g_rowptr[NN] = NE;
}
__global__ void scan_pass3() {
    int i = blockIdx.x * 512 + threadIdx.x;
    if (i < NN) {
        int r = g_rowptr[i] + g_boff[blockIdx.x];
        g_rowptr[i] = r;
        g_cursor[i] = r;
    }
}
__global__ void scatter_kernel(const void* __restrict__ ei) {
    int e = blockIdx.x * blockDim.x + threadIdx.x;
    if (e < NE) {
        int d = load_idx(ei, NE + e);
        int p = atomicAdd(&g_cursor[d], 1);
        g_srcs[p] = load_idx(ei, e);
    }
}

// ---------------- fp16 mma.sync GEMM: BM=128 BN=64, full K=128 panels ----------------
// 256 thr, 8 warps as 4(M)x2(N), warp tile 32x32. ~85 regs -> 3 CTAs/SM.
#define TSW 68   // words per smem row

__global__ void __launch_bounds__(256) gemm_f16_kernel(
    const __half* __restrict__ A, const __half* __restrict__ Wt,
    const float* __restrict__ bias, float* __restrict__ C,
    __half* __restrict__ XLH, int M, int F, int bm0)
{
    extern __shared__ unsigned smem[];
    unsigned* As = smem;               // 128 rows x 68 words
    unsigned* Bs = smem + 128 * TSW;   // 64 rows x 68 words
    const int N2 = 2 * F;

    int tid = threadIdx.x;
    int bm = (blockIdx.y + bm0) * 128;
    int bn = blockIdx.x * 64;

    int warpId = tid >> 5;
    int lane = tid & 31;
    int gid = lane >> 2;       // 0..7
    int tig = lane & 3;        // 0..3
    int warp_m = warpId & 3;   // 0..3 (32 rows each)
    int warp_n = warpId >> 2;  // 0..1 (32 cols each)

    float acc[2][4][4];
#pragma unroll
    for (int mt = 0; mt < 2; mt++)
#pragma unroll
        for (int nt = 0; nt < 4; nt++)
#pragma unroll
            for (int r = 0; r < 4; r++) acc[mt][nt][r] = 0.f;

    // A panel: thread t loads half of row (t>>1): 8 x cp16 = 128B
    {
        int row = tid >> 1;
        int half = tid & 1;
        int arow = bm + row; if (arow >= M) arow = M - 1;
        const __half* ap = A + (size_t)arow * 128 + half * 64;
        uint32_t as_d = (uint32_t)__cvta_generic_to_shared(&As[row * TSW + half * 32]);
#pragma unroll
        for (int j = 0; j < 8; j++) cp_async16(as_d + j * 16, ap + j * 8);
    }
    // B panel: thread t loads quarter of row (t>>2): 4 x cp16 = 64B
    {
        int row = tid >> 2;
        int q = tid & 3;
        const __half* bp = Wt + (size_t)(bn + row) * 128 + q * 32;
        uint32_t bs_d = (uint32_t)__cvta_generic_to_shared(&Bs[row * TSW + q * 16]);
#pragma unroll
        for (int j = 0; j < 4; j++) cp_async16(bs_d + j * 16, bp + j * 8);
    }
    CP_COMMIT();
    CP_WAIT0();
    __syncthreads();

#pragma unroll
    for (int kt = 0; kt < 8; kt++) {
        int kw = kt * 8 + tig;
        unsigned afr[2][4];
#pragma unroll
        for (int mt = 0; mt < 2; mt++) {
            int rm = warp_m * 32 + mt * 16 + gid;
            afr[mt][0] = As[(rm + 0) * TSW + kw];
            afr[mt][1] = As[(rm + 8) * TSW + kw];
            afr[mt][2] = As[(rm + 0) * TSW + kw + 4];
            afr[mt][3] = As[(rm + 8) * TSW + kw + 4];
        }
#pragma unroll
        for (int nt = 0; nt < 4; nt++) {
            int cn = warp_n * 32 + nt * 8 + gid;
            unsigned b0 = Bs[cn * TSW + kw];
            unsigned b1 = Bs[cn * TSW + kw + 4];
#pragma unroll
            for (int mt = 0; mt < 2; mt++) {
                asm volatile(
                    "mma.sync.aligned.m16n8k16.row.col.f32.f16.f16.f32 "
                    "{%0,%1,%2,%3}, {%4,%5,%6,%7}, {%8,%9}, {%0,%1,%2,%3};"
                    : "+f"(acc[mt][nt][0]), "+f"(acc[mt][nt][1]),
                      "+f"(acc[mt][nt][2]), "+f"(acc[mt][nt][3])
                    : "r"(afr[mt][0]), "r"(afr[mt][1]),
                      "r"(afr[mt][2]), "r"(afr[mt][3]),
                      "r"(b0), "r"(b1));
            }
        }
    }

    // epilogue: col<F -> xl fp16 to XLH; else fp32 [xr|res] to C at col-F
#pragma unroll
    for (int mt = 0; mt < 2; mt++) {
        int r0 = bm + warp_m * 32 + mt * 16 + gid;
        int r1 = r0 + 8;
#pragma unroll
        for (int nt = 0; nt < 4; nt++) {
            int col = bn + warp_n * 32 + nt * 8 + tig * 2;
            if (col < F) {
                if (r0 < M) {
                    __half2 h = __floats2half2_rn(acc[mt][nt][0], acc[mt][nt][1]);
                    *(__half2*)&XLH[(size_t)r0 * F + col] = h;
                }
                if (r1 < M) {
                    __half2 h = __floats2half2_rn(acc[mt][nt][2], acc[mt][nt][3]);
                    *(__half2*)&XLH[(size_t)r1 * F + col] = h;
                }
            } else {
                float bx = bias[col], by = bias[col + 1];
                if (r0 < M) {
                    float2 o = make_float2(acc[mt][nt][0] + bx, acc[mt][nt][1] + by);
                    *(float2*)&C[(size_t)r0 * N2 + col - F] = o;
                }
                if (r1 < M) {
                    float2 o = make_float2(acc[mt][nt][2] + bx, acc[mt][nt][3] + by);
                    *(float2*)&C[(size_t)r1 * N2 + col - F] = o;
                }
            }
        }
    }
}

// ---------------- fused edge pass: fp16 gather, chunked online softmax ----------------
// Processes node range [n0, n1).
template <int F>
__global__ void __launch_bounds__(256) edge_kernel(
    const __half* __restrict__ xlh, const float* __restrict__ C2,
    const float* __restrict__ att, float* __restrict__ outf,
    __half* __restrict__ outh, int apply_elu, int n0, int n1)
{
    constexpr int N2 = 2 * F;
    constexpr int V = F / 32;
    constexpr int EC = 4;
    int warp = n0 + ((blockIdx.x * blockDim.x + threadIdx.x) >> 5);
    int lane = threadIdx.x & 31;
    if (warp >= n1) return;
    int dst = warp;
    const int base = lane * V;

    float a[V], xrv[V], acc[V];
#pragma unroll
    for (int j = 0; j < V; j += 4) {
        float4 t = *(const float4*)&att[base + j];
        a[j] = t.x; a[j + 1] = t.y; a[j + 2] = t.z; a[j + 3] = t.w;
        float4 r = *(const float4*)&C2[(size_t)dst * N2 + base + j];
        xrv[j] = r.x; xrv[j + 1] = r.y; xrv[j + 2] = r.z; xrv[j + 3] = r.w;
    }
#pragma unroll
    for (int j = 0; j < V; j++) acc[j] = 0.f;

    float emax = -INFINITY, denom = 0.f;
    int p0 = g_rowptr[dst], p1 = g_rowptr[dst + 1];

    for (int p = p0; p < p1; p += EC) {
        int sidx[EC];
        float xlv[EC][V];
#pragma unroll
        for (int c = 0; c < EC; c++)
            sidx[c] = (p + c < p1) ? g_srcs[p + c] : -1;
#pragma unroll
        for (int c = 0; c < EC; c++) {
            if (sidx[c] >= 0) {
                const __half* src = xlh + (size_t)sidx[c] * F + base;
                if (F == 128) {
                    uint2 u = *(const uint2*)src;
                    float2 f0 = __half22float2(*(__half2*)&u.x);
                    float2 f1 = __half22float2(*(__half2*)&u.y);
                    xlv[c][0] = f0.x; xlv[c][1] = f0.y;
                    xlv[c][2] = f1.x; xlv[c][3] = f1.y;
                } else {
                    uint4 u = *(const uint4*)src;
                    float2 f0 = __half22float2(*(__half2*)&u.x);
                    float2 f1 = __half22float2(*(__half2*)&u.y);
                    float2 f2 = __half22float2(*(__half2*)&u.z);
                    float2 f3 = __half22float2(*(__half2*)&u.w);
                    xlv[c][0] = f0.x; xlv[c][1] = f0.y;
                    xlv[c][2] = f1.x; xlv[c][3] = f1.y;
                    xlv[c][4] = f2.x; xlv[c][5] = f2.y;
                    xlv[c][6] = f3.x; xlv[c][7] = f3.y;
                }
            } else {
#pragma unroll
                for (int j = 0; j < V; j++) xlv[c][j] = 0.f;
            }
        }
        float part[EC];
#pragma unroll
        for (int c = 0; c < EC; c++) {
            float s = 0.f;
#pragma unroll
            for (int j = 0; j < V; j++) {
                float h = xlv[c][j] + xrv[j];
                float lr = h > 0.f ? h : 0.2f * h;
                s = fmaf(a[j], lr, s);
            }
            part[c] = s;
        }
#pragma unroll
        for (int off = 16; off > 0; off >>= 1) {
#pragma unroll
            for (int c = 0; c < EC; c++)
                part[c] += __shfl_xor_sync(0xffffffffu, part[c], off);
        }
        float m = emax;
#pragma unroll
        for (int c = 0; c < EC; c++)
            if (sidx[c] >= 0) m = fmaxf(m, part[c]);
        float sc = __expf(emax - m);
        denom *= sc;
#pragma unroll
        for (int j = 0; j < V; j++) acc[j] *= sc;
#pragma unroll
        for (int c = 0; c < EC; c++) {
            float w = (sidx[c] >= 0) ? __expf(part[c] - m) : 0.f;
            denom += w;
#pragma unroll
            for (int j = 0; j < V; j++) acc[j] = fmaf(w, xlv[c][j], acc[j]);
        }
        emax = m;
    }

    float inv = 1.0f / (denom + 1e-16f);
    float ov[V];
#pragma unroll
    for (int j = 0; j < V; j += 4) {
        float4 r = *(const float4*)&C2[(size_t)dst * N2 + F + base + j];
        ov[j + 0] = fmaf(acc[j + 0], inv, r.x);
        ov[j + 1] = fmaf(acc[j + 1], inv, r.y);
        ov[j + 2] = fmaf(acc[j + 2], inv, r.z);
        ov[j + 3] = fmaf(acc[j + 3], inv, r.w);
    }
    if (apply_elu) {
#pragma unroll
        for (int j = 0; j < V; j++) ov[j] = ov[j] > 0.f ? ov[j] : expm1f(ov[j]);
    }
    if (outh) {
#pragma unroll
        for (int j = 0; j < V; j += 2) {
            __half2 h = __floats2half2_rn(ov[j], ov[j + 1]);
            *(__half2*)&outh[(size_t)dst * F + base + j] = h;
        }
    } else {
#pragma unroll
        for (int j = 0; j < V; j += 4) {
            float4 o = make_float4(ov[j], ov[j + 1], ov[j + 2], ov[j + 3]);
            *(float4*)&outf[(size_t)dst * F + base + j] = o;
        }
    }
}

// ---------------- launch: two-stream graph with edge1/GEMM2 pipelining --------------
extern "C" void kernel_launch(void* const* d_in, const int* in_sizes, int n_in,
                              void* d_out, int out_size)
{
    const float* x     = (const float*)d_in[0];
    const void*  ei    = d_in[1];
    const float* Wl1   = (const float*)d_in[2];
    const float* Wr1   = (const float*)d_in[3];
    const float* att1  = (const float*)d_in[4];
    const float* Wres1 = (const float*)d_in[5];
    const float* b1    = (const float*)d_in[6];
    const float* Wl2   = (const float*)d_in[7];
    const float* Wr2   = (const float*)d_in[8];
    const float* att2  = (const float*)d_in[9];
    const float* Wres2 = (const float*)d_in[10];
    const float* b2    = (const float*)d_in[11];

    __half *xh, *xlh1, *h1h, *xlh2, *W1h, *W2h;
    float *c1, *c2, *b1p, *b2p;
    int* histp;
    cudaGetSymbolAddress((void**)&xh,   g_xh);
    cudaGetSymbolAddress((void**)&xlh1, g_xlh1);
    cudaGetSymbolAddress((void**)&c1,   g_c1);
    cudaGetSymbolAddress((void**)&h1h,  g_h1h);
    cudaGetSymbolAddress((void**)&xlh2, g_xlh2);
    cudaGetSymbolAddress((void**)&c2,   g_c2);
    cudaGetSymbolAddress((void**)&W1h,  g_W1h);
    cudaGetSymbolAddress((void**)&W2h,  g_W2h);
    cudaGetSymbolAddress((void**)&b1p,  g_b1p);
    cudaGetSymbolAddress((void**)&b2p,  g_b2p);
    cudaGetSymbolAddress((void**)&histp, g_hist);

    const int GSMEM = (128 + 64) * TSW * 4;  // 52224 B
    cudaFuncSetAttribute(gemm_f16_kernel, cudaFuncAttributeMaxDynamicSharedMemorySize, GSMEM);

    const int MB = (NN + 127) / 128;  // 391

    static cudaStream_t s2 = nullptr;
    static cudaEvent_t evFork = nullptr, evJoin = nullptr, evE1a = nullptr, evG2a = nullptr;
    if (!s2) {
        cudaStreamCreateWithFlags(&s2, cudaStreamNonBlocking);
        cudaEventCreateWithFlags(&evFork, cudaEventDisableTiming);
        cudaEventCreateWithFlags(&evJoin, cudaEventDisableTiming);
        cudaEventCreateWithFlags(&evE1a, cudaEventDisableTiming);
        cudaEventCreateWithFlags(&evG2a, cudaEventDisableTiming);
    }

    // fork: CSR branch on s2
    cudaEventRecord(evFork, 0);
    cudaStreamWaitEvent(s2, evFork, 0);
    detect_kernel<<<1, 1024, 0, s2>>>((const unsigned int*)ei);
    cudaMemsetAsync(histp, 0, NN * sizeof(int), s2);
    hist_kernel<<<(NE + 255) / 256, 256, 0, s2>>>(ei);
    scan_pass1<<<SCAN_NB, 512, 0, s2>>>();
    scan_pass2<<<1, 128, 0, s2>>>();
    scan_pass3<<<SCAN_NB, 512, 0, s2>>>();
    scatter_kernel<<<(NE + 255) / 256, 256, 0, s2>>>(ei);
    cudaEventRecord(evJoin, s2);

    // compute branch (origin): conversions + layer-1 GEMM
    pack_all_kernel<<<(NT1 * DIN + NT2 * DH1 + 255) / 256, 256>>>(
        Wl1, Wr1, Wres1, b1, Wl2, Wr2, Wres2, b2);
    xconv_kernel<<<(NN * DIN / 4 + 255) / 256, 256>>>(x);
    gemm_f16_kernel<<<dim3(NT1 / 64, MB), 256, GSMEM>>>(xh, W1h, b1p, c1, xlh1,
                                                        NN, DH1, 0);

    // join CSR before edge1
    cudaStreamWaitEvent(0, evJoin, 0);

    // edge1 part a (nodes [0, SPLIT_ROWS)) -> enables GEMM2 part a on s2
    edge_kernel<DH1><<<(SPLIT_ROWS * 32 + 255) / 256, 256>>>(
        xlh1, c1, att1, nullptr, h1h, 1, 0, SPLIT_ROWS);
    cudaEventRecord(evE1a, 0);

    // GEMM2 part a on s2 (rows [0, SPLIT_ROWS)) overlaps edge1 part b
    cudaStreamWaitEvent(s2, evE1a, 0);
    gemm_f16_kernel<<<dim3(NT2 / 64, SPLIT_YB), 256, GSMEM, s2>>>(
        h1h, W2h, b2p, c2, xlh2, NN, DH2, 0);
    cudaEventRecord(evG2a, s2);

    // edge1 part b + GEMM2 part b on origin
    edge_kernel<DH1><<<((NN - SPLIT_ROWS) * 32 + 255) / 256, 256>>>(
        xlh1, c1, att1, nullptr, h1h, 1, SPLIT_ROWS, NN);
    gemm_f16_kernel<<<dim3(NT2 / 64, MB - SPLIT_YB), 256, GSMEM>>>(
        h1h, W2h, b2p, c2, xlh2, NN, DH2, SPLIT_YB);

    // edge2 needs both GEMM2 halves
    cudaStreamWaitEvent(0, evG2a, 0);
    edge_kernel<DH2><<<(NN * 32 + 255) / 256, 256>>>(
        xlh2, c2, att2, (float*)d_out, nullptr, 0, 0, NN);
}

// round 16
// speedup vs baseline: 1.0536x; 1.0536x over previous
#include <cuda_runtime.h>
#include <cuda_fp16.h>
#include <math.h>
#include <stdint.h>

#define NN 50000
#define NE 640000
#define DIN 128
#define DH1 128
#define DH2 256
#define NT1 (3 * DH1)   // 384
#define NT2 (3 * DH2)   // 768
#define SPLIT_ROWS 25088          // 196 blocks of 128
#define SPLIT_YB 196

// ---------------- device scratch ----------------
__device__ __half   g_xh[NN * DIN];
__device__ __half   g_xlh1[NN * DH1];
__device__ float    g_c1[NN * 2 * DH1];
__device__ __half   g_h1h[NN * DH1];
__device__ __half   g_xlh2[NN * DH2];
__device__ float    g_c2[NN * 2 * DH2];
__device__ __half   g_W1h[NT1 * DIN];
__device__ __half   g_W2h[NT2 * DH1];
__device__ float    g_b1p[NT1];
__device__ float    g_b2p[NT2];
__device__ int      g_rowptr[NN + 1];
__device__ int      g_hist[NN];
__device__ int      g_cursor[NN];
__device__ int      g_srcs[NE];
__device__ int      g_is64;
#define SCAN_NB 98
__device__ int      g_bsum[SCAN_NB];
__device__ int      g_boff[SCAN_NB];

__device__ __forceinline__ void cp_async16(uint32_t dst, const void* src) {
    asm volatile("cp.async.cg.shared.global [%0], [%1], 16;" :: "r"(dst), "l"(src));
}
#define CP_COMMIT() asm volatile("cp.async.commit_group;" ::: "memory")
#define CP_WAIT0()  asm volatile("cp.async.wait_group 0;" ::: "memory")

// ---------------- edge_index dtype detection ----------------
__global__ void detect_kernel(const unsigned int* __restrict__ w) {
    __shared__ int any_nonzero;
    if (threadIdx.x == 0) any_nonzero = 0;
    __syncthreads();
    unsigned int v = w[2 * threadIdx.x + 1];
    if (v != 0u) atomicOr(&any_nonzero, 1);
    __syncthreads();
    if (threadIdx.x == 0) g_is64 = any_nonzero ? 0 : 1;
}
__device__ __forceinline__ int load_idx(const void* ei, int i) {
    return g_is64 ? (int)((const long long*)ei)[i] : ((const int*)ei)[i];
}

// ---------------- x -> fp16 ----------------
__global__ void xconv_kernel(const float* __restrict__ x) {
    int i = blockIdx.x * blockDim.x + threadIdx.x;
    if (i < NN * DIN / 4) {
        float4 v = ((const float4*)x)[i];
        __half2 h0 = __floats2half2_rn(v.x, v.y);
        __half2 h1 = __floats2half2_rn(v.z, v.w);
        uint2 u;
        u.x = *(unsigned*)&h0; u.y = *(unsigned*)&h1;
        ((uint2*)g_xh)[i] = u;
    }
}

// ---------------- weight packing ----------------
__global__ void pack_all_kernel(
    const float* __restrict__ Wl1, const float* __restrict__ Wr1,
    const float* __restrict__ Wres1, const float* __restrict__ b1,
    const float* __restrict__ Wl2, const float* __restrict__ Wr2,
    const float* __restrict__ Wres2, const float* __restrict__ b2)
{
    int idx = blockIdx.x * blockDim.x + threadIdx.x;
    const int S1 = NT1 * DIN;
    const int S2 = NT2 * DH1;
    if (idx < S1) {
        int n = idx / DIN, k = idx % DIN;
        float v = (n < DH1) ? Wl1[k * DH1 + n]
                : (n < 2 * DH1) ? Wr1[k * DH1 + (n - DH1)]
                : Wres1[k * DH1 + (n - 2 * DH1)];
        g_W1h[idx] = __float2half(v);
    } else if (idx < S1 + S2) {
        int j = idx - S1;
        int n = j / DH1, k = j % DH1;
        float v = (n < DH2) ? Wl2[k * DH2 + n]
                : (n < 2 * DH2) ? Wr2[k * DH2 + (n - DH2)]
                : Wres2[k * DH2 + (n - 2 * DH2)];
        g_W2h[j] = __float2half(v);
    }
    if (idx < NT1) g_b1p[idx] = (idx < 2 * DH1) ? 0.f : b1[idx - 2 * DH1];
    if (idx < NT2) g_b2p[idx] = (idx < 2 * DH2) ? 0.f : b2[idx - 2 * DH2];
}

// ---------------- CSR build ----------------
__global__ void hist_kernel(const void* __restrict__ ei) {
    int e = blockIdx.x * blockDim.x + threadIdx.x;
    if (e < NE) atomicAdd(&g_hist[load_idx(ei, NE + e)], 1);
}
__global__ void scan_pass1() {
    __shared__ int sh[512];
    int t = threadIdx.x;
    int i = blockIdx.x * 512 + t;
    int v = (i < NN) ? g_hist[i] : 0;
    sh[t] = v;
    __syncthreads();
    for (int off = 1; off < 512; off <<= 1) {
        int u = (t >= off) ? sh[t - off] : 0;
        __syncthreads();
        sh[t] += u;
        __syncthreads();
    }
    if (i < NN) g_rowptr[i] = sh[t] - v;
    if (t == 511) g_bsum[blockIdx.x] = sh[511];
}
__global__ void scan_pass2() {
    __shared__ int sh[128];
    int t = threadIdx.x;
    int v = (t < SCAN_NB) ? g_bsum[t] : 0;
    sh[t] = v;
    __syncthreads();
    for (int off = 1; off < 128; off <<= 1) {
        int u = (t >= off) ? sh[t - off] : 0;
        __syncthreads();
        sh[t] += u;
        __syncthreads();
    }
    if (t < SCAN_NB) g_boff[t] = sh[t] - v;
    if (t == 0) g_rowptr[NN] = NE;
}
__global__ void scan_pass3() {
    int i = blockIdx.x * 512 + threadIdx.x;
    if (i < NN) {
        int r = g_rowptr[i] + g_boff[blockIdx.x];
        g_rowptr[i] = r;
        g_cursor[i] = r;
    }
}
__global__ void scatter_kernel(const void* __restrict__ ei) {
    int e = blockIdx.x * blockDim.x + threadIdx.x;
    if (e < NE) {
        int d = load_idx(ei, NE + e);
        int p = atomicAdd(&g_cursor[d], 1);
        g_srcs[p] = load_idx(ei, e);
    }
}

// ---------------- fp16 mma.sync GEMM: full K=128 panels, 256 thr, warp tile 64x32 --
// (R14 kernel + bm0 row-block offset for M-split launches)
#define TSW 68   // words per smem row

__global__ void __launch_bounds__(256) gemm_f16_kernel(
    const __half* __restrict__ A, const __half* __restrict__ Wt,
    const float* __restrict__ bias, float* __restrict__ C,
    __half* __restrict__ XLH, int M, int F, int bm0)
{
    extern __shared__ unsigned smem[];
    unsigned* As = smem;               // 128 rows x 68 words
    unsigned* Bs = smem + 128 * TSW;
    const int N2 = 2 * F;

    int tid = threadIdx.x;
    int bm = (blockIdx.y + bm0) * 128;
    int bn = blockIdx.x * 128;

    int warpId = tid >> 5;
    int lane = tid & 31;
    int gid = lane >> 2;       // 0..7
    int tig = lane & 3;        // 0..3
    int warp_m = warpId >> 2;  // 0..1 (64 rows each)
    int warp_n = warpId & 3;   // 0..3 (32 cols each)

    float acc[4][4][4];
#pragma unroll
    for (int mt = 0; mt < 4; mt++)
#pragma unroll
        for (int nt = 0; nt < 4; nt++)
#pragma unroll
            for (int r = 0; r < 4; r++) acc[mt][nt][r] = 0.f;

    // load full panels: thread t loads half of A row (t>>1) and half of B row (t>>1)
    int row = tid >> 1;
    int half = tid & 1;
    int arow = bm + row; if (arow >= M) arow = M - 1;
    const __half* ap = A + (size_t)arow * 128 + half * 64;
    const __half* bp = Wt + (size_t)(bn + row) * 128 + half * 64;
    uint32_t as_d = (uint32_t)__cvta_generic_to_shared(&As[row * TSW + half * 32]);
    uint32_t bs_d = (uint32_t)__cvta_generic_to_shared(&Bs[row * TSW + half * 32]);
#pragma unroll
    for (int j = 0; j < 8; j++) {
        cp_async16(as_d + j * 16, ap + j * 8);
        cp_async16(bs_d + j * 16, bp + j * 8);
    }
    CP_COMMIT();
    CP_WAIT0();
    __syncthreads();

#pragma unroll
    for (int kt = 0; kt < 8; kt++) {
        int kw = kt * 8 + tig;
        unsigned afr[4][4];
#pragma unroll
        for (int mt = 0; mt < 4; mt++) {
            int rm = warp_m * 64 + mt * 16 + gid;
            afr[mt][0] = As[(rm + 0) * TSW + kw];
            afr[mt][1] = As[(rm + 8) * TSW + kw];
            afr[mt][2] = As[(rm + 0) * TSW + kw + 4];
            afr[mt][3] = As[(rm + 8) * TSW + kw + 4];
        }
#pragma unroll
        for (int nt = 0; nt < 4; nt++) {
            int cn = warp_n * 32 + nt * 8 + gid;
            unsigned b0 = Bs[cn * TSW + kw];
            unsigned b1 = Bs[cn * TSW + kw + 4];
#pragma unroll
            for (int mt = 0; mt < 4; mt++) {
                asm volatile(
                    "mma.sync.aligned.m16n8k16.row.col.f32.f16.f16.f32 "
                    "{%0,%1,%2,%3}, {%4,%5,%6,%7}, {%8,%9}, {%0,%1,%2,%3};"
                    : "+f"(acc[mt][nt][0]), "+f"(acc[mt][nt][1]),
                      "+f"(acc[mt][nt][2]), "+f"(acc[mt][nt][3])
                    : "r"(afr[mt][0]), "r"(afr[mt][1]),
                      "r"(afr[mt][2]), "r"(afr[mt][3]),
                      "r"(b0), "r"(b1));
            }
        }
    }

    // epilogue: col<F -> xl as fp16 to XLH; else fp32 [xr|res] to C at col-F
#pragma unroll
    for (int mt = 0; mt < 4; mt++) {
        int r0 = bm + warp_m * 64 + mt * 16 + gid;
        int r1 = r0 + 8;
#pragma unroll
        for (int nt = 0; nt < 4; nt++) {
            int col = bn + warp_n * 32 + nt * 8 + tig * 2;
            if (col < F) {
                if (r0 < M) {
                    __half2 h = __floats2half2_rn(acc[mt][nt][0], acc[mt][nt][1]);
                    *(__half2*)&XLH[(size_t)r0 * F + col] = h;
                }
                if (r1 < M) {
                    __half2 h = __floats2half2_rn(acc[mt][nt][2], acc[mt][nt][3]);
                    *(__half2*)&XLH[(size_t)r1 * F + col] = h;
                }
            } else {
                float bx = bias[col], by = bias[col + 1];
                if (r0 < M) {
                    float2 o = make_float2(acc[mt][nt][0] + bx, acc[mt][nt][1] + by);
                    *(float2*)&C[(size_t)r0 * N2 + col - F] = o;
                }
                if (r1 < M) {
                    float2 o = make_float2(acc[mt][nt][2] + bx, acc[mt][nt][3] + by);
                    *(float2*)&C[(size_t)r1 * N2 + col - F] = o;
                }
            }
        }
    }
}

// ---------------- fused edge pass: fp16 gather, chunked online softmax ----------------
template <int F>
__global__ void __launch_bounds__(256) edge_kernel(
    const __half* __restrict__ xlh, const float* __restrict__ C2,
    const float* __restrict__ att, float* __restrict__ outf,
    __half* __restrict__ outh, int apply_elu, int n0, int n1)
{
    constexpr int N2 = 2 * F;
    constexpr int V = F / 32;
    constexpr int EC = 4;
    int warp = n0 + ((blockIdx.x * blockDim.x + threadIdx.x) >> 5);
    int lane = threadIdx.x & 31;
    if (warp >= n1) return;
    int dst = warp;
    const int base = lane * V;

    float a[V], xrv[V], acc[V];
#pragma unroll
    for (int j = 0; j < V; j += 4) {
        float4 t = *(const float4*)&att[base + j];
        a[j] = t.x; a[j + 1] = t.y; a[j + 2] = t.z; a[j + 3] = t.w;
        float4 r = *(const float4*)&C2[(size_t)dst * N2 + base + j];
        xrv[j] = r.x; xrv[j + 1] = r.y; xrv[j + 2] = r.z; xrv[j + 3] = r.w;
    }
#pragma unroll
    for (int j = 0; j < V; j++) acc[j] = 0.f;

    float emax = -INFINITY, denom = 0.f;
    int p0 = g_rowptr[dst], p1 = g_rowptr[dst + 1];

    for (int p = p0; p < p1; p += EC) {
        int sidx[EC];
        float xlv[EC][V];
#pragma unroll
        for (int c = 0; c < EC; c++)
            sidx[c] = (p + c < p1) ? g_srcs[p + c] : -1;
#pragma unroll
        for (int c = 0; c < EC; c++) {
            if (sidx[c] >= 0) {
                const __half* src = xlh + (size_t)sidx[c] * F + base;
                if (F == 128) {
                    uint2 u = *(const uint2*)src;
                    float2 f0 = __half22float2(*(__half2*)&u.x);
                    float2 f1 = __half22float2(*(__half2*)&u.y);
                    xlv[c][0] = f0.x; xlv[c][1] = f0.y;
                    xlv[c][2] = f1.x; xlv[c][3] = f1.y;
                } else {
                    uint4 u = *(const uint4*)src;
                    float2 f0 = __half22float2(*(__half2*)&u.x);
                    float2 f1 = __half22float2(*(__half2*)&u.y);
                    float2 f2 = __half22float2(*(__half2*)&u.z);
                    float2 f3 = __half22float2(*(__half2*)&u.w);
                    xlv[c][0] = f0.x; xlv[c][1] = f0.y;
                    xlv[c][2] = f1.x; xlv[c][3] = f1.y;
                    xlv[c][4] = f2.x; xlv[c][5] = f2.y;
                    xlv[c][6] = f3.x; xlv[c][7] = f3.y;
                }
            } else {
#pragma unroll
                for (int j = 0; j < V; j++) xlv[c][j] = 0.f;
            }
        }
        float part[EC];
#pragma unroll
        for (int c = 0; c < EC; c++) {
            float s = 0.f;
#pragma unroll
            for (int j = 0; j < V; j++) {
                float h = xlv[c][j] + xrv[j];
                float lr = h > 0.f ? h : 0.2f * h;
                s = fmaf(a[j], lr, s);
            }
            part[c] = s;
        }
#pragma unroll
        for (int off = 16; off > 0; off >>= 1) {
#pragma unroll
            for (int c = 0; c < EC; c++)
                part[c] += __shfl_xor_sync(0xffffffffu, part[c], off);
        }
        float m = emax;
#pragma unroll
        for (int c = 0; c < EC; c++)
            if (sidx[c] >= 0) m = fmaxf(m, part[c]);
        float sc = __expf(emax - m);
        denom *= sc;
#pragma unroll
        for (int j = 0; j < V; j++) acc[j] *= sc;
#pragma unroll
        for (int c = 0; c < EC; c++) {
            float w = (sidx[c] >= 0) ? __expf(part[c] - m) : 0.f;
            denom += w;
#pragma unroll
            for (int j = 0; j < V; j++) acc[j] = fmaf(w, xlv[c][j], acc[j]);
        }
        emax = m;
    }

    float inv = 1.0f / (denom + 1e-16f);
    float ov[V];
#pragma unroll
    for (int j = 0; j < V; j += 4) {
        float4 r = *(const float4*)&C2[(size_t)dst * N2 + F + base + j];
        ov[j + 0] = fmaf(acc[j + 0], inv, r.x);
        ov[j + 1] = fmaf(acc[j + 1], inv, r.y);
        ov[j + 2] = fmaf(acc[j + 2], inv, r.z);
        ov[j + 3] = fmaf(acc[j + 3], inv, r.w);
    }
    if (apply_elu) {
#pragma unroll
        for (int j = 0; j < V; j++) ov[j] = ov[j] > 0.f ? ov[j] : expm1f(ov[j]);
    }
    if (outh) {
#pragma unroll
        for (int j = 0; j < V; j += 2) {
            __half2 h = __floats2half2_rn(ov[j], ov[j + 1]);
            *(__half2*)&outh[(size_t)dst * F + base + j] = h;
        }
    } else {
#pragma unroll
        for (int j = 0; j < V; j += 4) {
            float4 o = make_float4(ov[j], ov[j + 1], ov[j + 2], ov[j + 3]);
            *(float4*)&outf[(size_t)dst * F + base + j] = o;
        }
    }
}

// ---------------- launch: two-stream graph, CSR overlap + edge1/GEMM2 pipelining ----
extern "C" void kernel_launch(void* const* d_in, const int* in_sizes, int n_in,
                              void* d_out, int out_size)
{
    const float* x     = (const float*)d_in[0];
    const void*  ei    = d_in[1];
    const float* Wl1   = (const float*)d_in[2];
    const float* Wr1   = (const float*)d_in[3];
    const float* att1  = (const float*)d_in[4];
    const float* Wres1 = (const float*)d_in[5];
    const float* b1    = (const float*)d_in[6];
    const float* Wl2   = (const float*)d_in[7];
    const float* Wr2   = (const float*)d_in[8];
    const float* att2  = (const float*)d_in[9];
    const float* Wres2 = (const float*)d_in[10];
    const float* b2    = (const float*)d_in[11];

    __half *xh, *xlh1, *h1h, *xlh2, *W1h, *W2h;
    float *c1, *c2, *b1p, *b2p;
    int* histp;
    cudaGetSymbolAddress((void**)&xh,   g_xh);
    cudaGetSymbolAddress((void**)&xlh1, g_xlh1);
    cudaGetSymbolAddress((void**)&c1,   g_c1);
    cudaGetSymbolAddress((void**)&h1h,  g_h1h);
    cudaGetSymbolAddress((void**)&xlh2, g_xlh2);
    cudaGetSymbolAddress((void**)&c2,   g_c2);
    cudaGetSymbolAddress((void**)&W1h,  g_W1h);
    cudaGetSymbolAddress((void**)&W2h,  g_W2h);
    cudaGetSymbolAddress((void**)&b1p,  g_b1p);
    cudaGetSymbolAddress((void**)&b2p,  g_b2p);
    cudaGetSymbolAddress((void**)&histp, g_hist);

    const int GSMEM = 2 * 128 * TSW * 4;  // 69632 B
    cudaFuncSetAttribute(gemm_f16_kernel, cudaFuncAttributeMaxDynamicSharedMemorySize, GSMEM);

    const int MB = (NN + 127) / 128;  // 391

    static cudaStream_t s2 = nullptr;
    static cudaEvent_t evFork = nullptr, evJoin = nullptr, evE1a = nullptr, evG2a = nullptr;
    if (!s2) {
        cudaStreamCreateWithFlags(&s2, cudaStreamNonBlocking);
        cudaEventCreateWithFlags(&evFork, cudaEventDisableTiming);
        cudaEventCreateWithFlags(&evJoin, cudaEventDisableTiming);
        cudaEventCreateWithFlags(&evE1a, cudaEventDisableTiming);
        cudaEventCreateWithFlags(&evG2a, cudaEventDisableTiming);
    }

    // fork: CSR branch on s2
    cudaEventRecord(evFork, 0);
    cudaStreamWaitEvent(s2, evFork, 0);
    detect_kernel<<<1, 1024, 0, s2>>>((const unsigned int*)ei);
    cudaMemsetAsync(histp, 0, NN * sizeof(int), s2);
    hist_kernel<<<(NE + 255) / 256, 256, 0, s2>>>(ei);
    scan_pass1<<<SCAN_NB, 512, 0, s2>>>();
    scan_pass2<<<1, 128, 0, s2>>>();
    scan_pass3<<<SCAN_NB, 512, 0, s2>>>();
    scatter_kernel<<<(NE + 255) / 256, 256, 0, s2>>>(ei);
    cudaEventRecord(evJoin, s2);

    // compute branch (origin): conversions + layer-1 GEMM (BM=128, BN=128)
    pack_all_kernel<<<(NT1 * DIN + NT2 * DH1 + 255) / 256, 256>>>(
        Wl1, Wr1, Wres1, b1, Wl2, Wr2, Wres2, b2);
    xconv_kernel<<<(NN * DIN / 4 + 255) / 256, 256>>>(x);
    gemm_f16_kernel<<<dim3(NT1 / 128, MB), 256, GSMEM>>>(xh, W1h, b1p, c1, xlh1,
                                                         NN, DH1, 0);

    // join CSR before edge1
    cudaStreamWaitEvent(0, evJoin, 0);

    // edge1 part a (nodes [0, SPLIT_ROWS)) -> enables GEMM2 part a on s2
    edge_kernel<DH1><<<(SPLIT_ROWS * 32 + 255) / 256, 256>>>(
        xlh1, c1, att1, nullptr, h1h, 1, 0, SPLIT_ROWS);
    cudaEventRecord(evE1a, 0);

    // GEMM2 part a on s2 (rows [0, SPLIT_ROWS)) overlaps edge1 part b
    cudaStreamWaitEvent(s2, evE1a, 0);
    gemm_f16_kernel<<<dim3(NT2 / 128, SPLIT_YB), 256, GSMEM, s2>>>(
        h1h, W2h, b2p, c2, xlh2, NN, DH2, 0);
    cudaEventRecord(evG2a, s2);

    // edge1 part b + GEMM2 part b on origin
    edge_kernel<DH1><<<((NN - SPLIT_ROWS) * 32 + 255) / 256, 256>>>(
        xlh1, c1, att1, nullptr, h1h, 1, SPLIT_ROWS, NN);
    gemm_f16_kernel<<<dim3(NT2 / 128, MB - SPLIT_YB), 256, GSMEM>>>(
        h1h, W2h, b2p, c2, xlh2, NN, DH2, SPLIT_YB);

    // edge2 needs both GEMM2 halves
    cudaStreamWaitEvent(0, evG2a, 0);
    edge_kernel<DH2><<<(NN * 32 + 255) / 256, 256>>>(
        xlh2, c2, att2, (float*)d_out, nullptr, 0, 0, NN);
}